// round 16
// baseline (speedup 1.0000x reference)
#include <cuda_runtime.h>
#include <cuda_fp16.h>
#include <stdint.h>

#define NODE_DIM   128
#define GATE_HID   64
#define OUT_DIM    128
#define NUM_GRAPHS 16384
#define CHUNK      512
#define THREADS    256

#define B_STRIDE_H 136   // halves; warp-private h slice stride
#define A_SLICE_H  (16 * B_STRIDE_H)

// Scratch: per-graph sum of g*h [B,128] and per-graph sum of g [B].
// Invariant: zero at kernel_launch entry (loader zero-init covers call #1;
// final_kernel re-zeros its exclusive slice after consuming it).
__device__ float g_S[NUM_GRAPHS * OUT_DIM];
__device__ float g_cnt[NUM_GRAPHS];
// Fragment-ordered fp16 Wg1, paired over ks:
// g_Bf4[(nt*4 + kp)*32 + lane] = {b(2kp).x, b(2kp).y, b(2kp+1).x, b(2kp+1).y}
__device__ uint4 g_Bf4[8 * 4 * 32];

static __device__ __forceinline__ uint32_t u32_of(__half2 h) {
    union { __half2 h; uint32_t u; } c; c.h = h; return c.u;
}
static __device__ __forceinline__ __half2 h2_of(uint32_t u) {
    union { uint32_t u; __half2 h; } c; c.u = u; return c.h;
}
static __device__ __forceinline__ uint32_t cvt2(float2 v) {
    return u32_of(__floats2half2_rn(v.x, v.y));
}
static __device__ __forceinline__ uint32_t pack2(float a, float b) {
    return u32_of(__floats2half2_rn(a, b));
}

// ---------------------------------------------------------------------------
// Warp-level fp16 MMA with fp16 accumulate
// ---------------------------------------------------------------------------
static __device__ __forceinline__ void mma16816_f16(
    uint32_t* d, uint32_t a0, uint32_t a1, uint32_t a2, uint32_t a3,
    uint32_t b0, uint32_t b1)
{
    asm volatile(
        "mma.sync.aligned.m16n8k16.row.col.f16.f16.f16.f16 "
        "{%0,%1}, {%2,%3,%4,%5}, {%6,%7}, {%0,%1};"
        : "+r"(d[0]), "+r"(d[1])
        : "r"(a0), "r"(a1), "r"(a2), "r"(a3), "r"(b0), "r"(b1));
}

// batch may be int32 or int64 (layout-detected; see earlier rounds)
static __device__ __forceinline__ int batch_at(const void* p, int i, bool is64) {
    if (is64) return (int)(((const long long*)p)[i]);
    return ((const int*)p)[i];
}

// ---------------------------------------------------------------------------
// prep: Wg1 [128,64] -> ks-paired fragment table (1024 uint4 entries)
// ---------------------------------------------------------------------------
__global__ void prep_kernel(const float* __restrict__ Wg1) {
    int idx = blockIdx.x * blockDim.x + threadIdx.x;
    if (idx < 1024) {
        int lane = idx & 31, e = idx >> 5;   // e = nt*4 + kp
        int kp = e & 3, nt = e >> 2;
        int gq = lane >> 2, tq = lane & 3;
        int n  = nt * 8 + gq;
        int ka = (2 * kp) * 16 + tq * 2;      // ks = 2kp
        int kb = (2 * kp + 1) * 16 + tq * 2;  // ks = 2kp+1
        uint4 v;
        v.x = pack2(Wg1[ka * GATE_HID + n],       Wg1[(ka + 1) * GATE_HID + n]);
        v.y = pack2(Wg1[(ka + 8) * GATE_HID + n], Wg1[(ka + 9) * GATE_HID + n]);
        v.z = pack2(Wg1[kb * GATE_HID + n],       Wg1[(kb + 1) * GATE_HID + n]);
        v.w = pack2(Wg1[(kb + 8) * GATE_HID + n], Wg1[(kb + 9) * GATE_HID + n]);
        g_Bf4[idx] = v;
    }
}

// ---------------------------------------------------------------------------
// Fused pass per 512-node chunk; warp owns 64 rows as 4 sub-tiles of 16.
// Pipelined loads (a 16-LDG group always in flight); B fragments via LDS.128
// feeding two HMMAs each; scatter accumulators carried across all 4 subs.
// ---------------------------------------------------------------------------
__global__ __launch_bounds__(THREADS, 3)
void fused_kernel(const float* __restrict__ h_nodes,
                  const void*  __restrict__ batch,
                  const float* __restrict__ bg1,
                  const float* __restrict__ Wg2,
                  const float* __restrict__ bg2,
                  int N)
{
    extern __shared__ char sm[];
    uint4*  smT4 = (uint4*)sm;                             // 16384 B
    __half* smHA = (__half*)(sm + 16384);                  // 34816 B
    int*    sh_b = (int*)(sm + 51200);                     // 2048 B
    float2* sh_bw = (float2*)(sm + 53248);                 // 512 B (b1,w2)
                                                           // total 53760

    const int tid  = threadIdx.x;
    const int wid  = tid >> 5;
    const int lane = tid & 31;
    const int gq   = lane >> 2;
    const int tq   = lane & 3;
    const int base = blockIdx.x * CHUNK;
    const int nn   = min(CHUNK, N - base);

    const bool is64 = (((const int*)batch)[N - 1] == 0);

    #pragma unroll 4
    for (int i = tid; i < 1024; i += THREADS)
        smT4[i] = g_Bf4[i];
    if (tid < GATE_HID) sh_bw[tid] = make_float2(bg1[tid], Wg2[tid]);
    #pragma unroll 2
    for (int i = tid; i < CHUNK; i += THREADS)
        sh_b[i] = (i < nn) ? batch_at(batch, base + i, is64) : 0;
    __syncthreads();

    __half* ws = smHA + wid * A_SLICE_H;
    const float b2 = bg2[0];
    const float2 z2 = make_float2(0.f, 0.f);

    float2 f0[4], f1[4], f2[4], f3[4];

#define LOADG(grp, hp0, hp1, vv0, vv1)                                   \
    do {                                                                 \
        _Pragma("unroll")                                                \
        for (int kk = 0; kk < 4; ++kk) {                                 \
            const int kb = ((grp) * 4 + kk) * 16 + tq * 2;               \
            f0[kk] = (vv0) ? *(const float2*)((hp0) + kb)     : z2;      \
            f2[kk] = (vv0) ? *(const float2*)((hp0) + kb + 8) : z2;      \
            f1[kk] = (vv1) ? *(const float2*)((hp1) + kb)     : z2;      \
            f3[kk] = (vv1) ? *(const float2*)((hp1) + kb + 8) : z2;      \
        }                                                                \
    } while (0)

#define CVT_STS(grp, A0v, A1v, A2v, A3v)                                 \
    do {                                                                 \
        _Pragma("unroll")                                                \
        for (int kk = 0; kk < 4; ++kk) {                                 \
            A0v[kk] = cvt2(f0[kk]); A1v[kk] = cvt2(f1[kk]);              \
            A2v[kk] = cvt2(f2[kk]); A3v[kk] = cvt2(f3[kk]);              \
            const int kb = ((grp) * 4 + kk) * 16 + tq * 2;               \
            *(uint32_t*)(ws + gq * B_STRIDE_H + kb)           = A0v[kk]; \
            *(uint32_t*)(ws + gq * B_STRIDE_H + kb + 8)       = A2v[kk]; \
            *(uint32_t*)(ws + (gq + 8) * B_STRIDE_H + kb)     = A1v[kk]; \
            *(uint32_t*)(ws + (gq + 8) * B_STRIDE_H + kb + 8) = A3v[kk]; \
        }                                                                \
    } while (0)

// B via LDS.128: one uint4 = fragments for ks=2kp and 2kp+1 of column tile nt
#define MMA_GRP(grp, A0v, A1v, A2v, A3v)                                 \
    do {                                                                 \
        _Pragma("unroll")                                                \
        for (int kpl = 0; kpl < 2; ++kpl) {                              \
            const int kp = (grp) * 2 + kpl;                              \
            _Pragma("unroll")                                            \
            for (int nt = 0; nt < 8; ++nt) {                             \
                uint4 b = smT4[(nt * 4 + kp) * 32 + lane];               \
                mma16816_f16(d[nt], A0v[2*kpl],   A1v[2*kpl],            \
                             A2v[2*kpl],   A3v[2*kpl],   b.x, b.y);      \
                mma16816_f16(d[nt], A0v[2*kpl+1], A1v[2*kpl+1],          \
                             A2v[2*kpl+1], A3v[2*kpl+1], b.z, b.w);      \
            }                                                            \
        }                                                                \
    } while (0)

    const int wbeg = wid * 64;
    const float* hr0 = h_nodes + (size_t)(base + wbeg + gq) * NODE_DIM;
    const float* hr1 = hr0 + 8 * NODE_DIM;
    bool v0 = (base + wbeg + gq) < N;
    bool v1 = (base + wbeg + gq + 8) < N;

    // cross-sub scatter state
    const bool any = wbeg < nn;
    int   cur  = any ? sh_b[wbeg] : 0;
    float a0 = 0.f, a1 = 0.f, a2 = 0.f, a3 = 0.f, accG = 0.f;

    // prologue: grp0 of sub 0 in flight
    LOADG(0, hr0, hr1, v0, v1);

    #pragma unroll 1
    for (int sub = 0; sub < 4; ++sub) {
        const int rbeg = wbeg + sub * 16;
        uint32_t d[8][2];
        #pragma unroll
        for (int nt = 0; nt < 8; ++nt) { d[nt][0] = 0u; d[nt][1] = 0u; }

        uint32_t A0[4], A1[4], A2[4], A3[4];
        CVT_STS(0, A0, A1, A2, A3);
        LOADG(1, hr0, hr1, v0, v1);      // grp1 latency covered by grp0 MMAs
        MMA_GRP(0, A0, A1, A2, A3);
        CVT_STS(1, A0, A1, A2, A3);
        MMA_GRP(1, A0, A1, A2, A3);

        // --- gate epilogue
        float s0 = 0.0f, s1 = 0.0f;
        #pragma unroll
        for (int nt = 0; nt < 8; ++nt) {
            int c0 = nt * 8 + tq * 2;
            float2 bwa = sh_bw[c0];
            float2 bwb = sh_bw[c0 + 1];
            float2 lo = __half22float2(h2_of(d[nt][0]));   // row gq
            float2 hi = __half22float2(h2_of(d[nt][1]));   // row gq+8
            s0 = fmaf(fmaxf(lo.x + bwa.x, 0.0f), bwa.y, s0);
            s0 = fmaf(fmaxf(lo.y + bwb.x, 0.0f), bwb.y, s0);
            s1 = fmaf(fmaxf(hi.x + bwa.x, 0.0f), bwa.y, s1);
            s1 = fmaf(fmaxf(hi.y + bwb.x, 0.0f), bwb.y, s1);
        }
        s0 += __shfl_xor_sync(0xffffffffu, s0, 1);
        s0 += __shfl_xor_sync(0xffffffffu, s0, 2);
        s1 += __shfl_xor_sync(0xffffffffu, s1, 1);
        s1 += __shfl_xor_sync(0xffffffffu, s1, 2);
        s0 = 1.0f / (1.0f + __expf(-(s0 + b2)));
        s1 = 1.0f / (1.0f + __expf(-(s1 + b2)));

        // prefetch next sub's grp0 under the scatter
        if (sub < 3) {
            hr0 += 16 * NODE_DIM;
            hr1 += 16 * NODE_DIM;
            v0 = (base + rbeg + 16 + gq) < N;
            v1 = (base + rbeg + 16 + gq + 8) < N;
            LOADG(0, hr0, hr1, v0, v1);
        }

        // --- scatter these 16 nodes; accumulators persist across subs
        const int nend = min(rbeg + 16, nn);
        #pragma unroll
        for (int lr = 0; lr < 16; ++lr) {
            int n = rbeg + lr;
            if (n >= nend) break;
            int b = sh_b[n];
            if (b != cur) {
                float* dst = g_S + (size_t)cur * OUT_DIM + lane * 4;
                atomicAdd(dst + 0, a0); atomicAdd(dst + 1, a1);
                atomicAdd(dst + 2, a2); atomicAdd(dst + 3, a3);
                if (lane == 0) atomicAdd(&g_cnt[cur], accG);
                a0 = a1 = a2 = a3 = 0.f; accG = 0.f; cur = b;
            }
            float g = __shfl_sync(0xffffffffu, (lr < 8) ? s0 : s1, (lr & 7) * 4);
            const __half2* hp = (const __half2*)(ws + lr * B_STRIDE_H + lane * 4);
            float2 h01 = __half22float2(hp[0]);
            float2 h23 = __half22float2(hp[1]);
            a0 = fmaf(g, h01.x, a0); a1 = fmaf(g, h01.y, a1);
            a2 = fmaf(g, h23.x, a2); a3 = fmaf(g, h23.y, a3);
            accG += g;
        }
    }

    // final flush (once per warp)
    if (any) {
        float* dst = g_S + (size_t)cur * OUT_DIM + lane * 4;
        atomicAdd(dst + 0, a0); atomicAdd(dst + 1, a1);
        atomicAdd(dst + 2, a2); atomicAdd(dst + 3, a3);
        if (lane == 0) atomicAdd(&g_cnt[cur], accG);
    }
#undef LOADG
#undef CVT_STS
#undef MMA_GRP
}

// ---------------------------------------------------------------------------
// Final: out = S @ Wp + cnt (x) bp.  32 graphs/block, thread = 4 graphs x 4
// outputs. Then re-zero this block's scratch slice.
// ---------------------------------------------------------------------------
#define FIN_GRAPHS 32

__global__ __launch_bounds__(THREADS, 2)
void final_kernel(const float* __restrict__ Wp,
                  const float* __restrict__ bp,
                  float* __restrict__ out)
{
    extern __shared__ float smf[];
    float* sWp  = smf;                        // [128][128] d-major
    float* sS   = smf + NODE_DIM * OUT_DIM;   // [32][128]
    float* scnt = sS + FIN_GRAPHS * NODE_DIM; // 32 floats

    const int tid = threadIdx.x;
    const int gr  = tid >> 5;
    const int oc  = tid & 31;
    const int gblk = blockIdx.x * FIN_GRAPHS;

    #pragma unroll 16
    for (int i = tid; i < NODE_DIM * OUT_DIM / 4; i += THREADS)
        ((float4*)sWp)[i] = ((const float4*)Wp)[i];
    #pragma unroll 4
    for (int i = tid; i < FIN_GRAPHS * NODE_DIM / 4; i += THREADS) {
        int g = i >> 5, q = i & 31;
        ((float4*)(sS + g * NODE_DIM))[q] =
            ((const float4*)(g_S + (size_t)(gblk + g) * NODE_DIM))[q];
    }
    if (tid < FIN_GRAPHS) scnt[tid] = g_cnt[gblk + tid];
    __syncthreads();

    const float4 bpv = ((const float4*)bp)[oc];
    float acc[4][4];
    #pragma unroll
    for (int i = 0; i < 4; ++i) {
        float c = scnt[gr * 4 + i];
        acc[i][0] = c * bpv.x; acc[i][1] = c * bpv.y;
        acc[i][2] = c * bpv.z; acc[i][3] = c * bpv.w;
    }

    #pragma unroll 4
    for (int dq = 0; dq < NODE_DIM / 4; ++dq) {
        float4 w0 = ((const float4*)(sWp + (dq * 4 + 0) * OUT_DIM))[oc];
        float4 w1 = ((const float4*)(sWp + (dq * 4 + 1) * OUT_DIM))[oc];
        float4 w2 = ((const float4*)(sWp + (dq * 4 + 2) * OUT_DIM))[oc];
        float4 w3 = ((const float4*)(sWp + (dq * 4 + 3) * OUT_DIM))[oc];
        #pragma unroll
        for (int i = 0; i < 4; ++i) {
            float4 sv = ((const float4*)(sS + (gr * 4 + i) * NODE_DIM))[dq];
            acc[i][0] = fmaf(sv.x, w0.x, acc[i][0]);
            acc[i][1] = fmaf(sv.x, w0.y, acc[i][1]);
            acc[i][2] = fmaf(sv.x, w0.z, acc[i][2]);
            acc[i][3] = fmaf(sv.x, w0.w, acc[i][3]);
            acc[i][0] = fmaf(sv.y, w1.x, acc[i][0]);
            acc[i][1] = fmaf(sv.y, w1.y, acc[i][1]);
            acc[i][2] = fmaf(sv.y, w1.z, acc[i][2]);
            acc[i][3] = fmaf(sv.y, w1.w, acc[i][3]);
            acc[i][0] = fmaf(sv.z, w2.x, acc[i][0]);
            acc[i][1] = fmaf(sv.z, w2.y, acc[i][1]);
            acc[i][2] = fmaf(sv.z, w2.z, acc[i][2]);
            acc[i][3] = fmaf(sv.z, w2.w, acc[i][3]);
            acc[i][0] = fmaf(sv.w, w3.x, acc[i][0]);
            acc[i][1] = fmaf(sv.w, w3.y, acc[i][1]);
            acc[i][2] = fmaf(sv.w, w3.z, acc[i][2]);
            acc[i][3] = fmaf(sv.w, w3.w, acc[i][3]);
        }
    }

    #pragma unroll
    for (int i = 0; i < 4; ++i) {
        float4 v = make_float4(acc[i][0], acc[i][1], acc[i][2], acc[i][3]);
        ((float4*)(out + (size_t)(gblk + gr * 4 + i) * OUT_DIM))[oc] = v;
    }

    __syncthreads();
    float4 z = make_float4(0.f, 0.f, 0.f, 0.f);
    float4* srow4 = (float4*)(g_S + (size_t)gblk * NODE_DIM);
    #pragma unroll 4
    for (int i = tid; i < FIN_GRAPHS * NODE_DIM / 4; i += THREADS) srow4[i] = z;
    if (tid < FIN_GRAPHS) g_cnt[gblk + tid] = 0.0f;
}

// ---------------------------------------------------------------------------
extern "C" void kernel_launch(void* const* d_in, const int* in_sizes, int n_in,
                              void* d_out, int out_size)
{
    const float* h_nodes = (const float*)d_in[0];
    const void*  batch   = d_in[1];
    const float* Wg1     = (const float*)d_in[2];
    const float* bg1     = (const float*)d_in[3];
    const float* Wg2     = (const float*)d_in[4];
    const float* bg2     = (const float*)d_in[5];
    const float* Wp      = (const float*)d_in[6];
    const float* bp      = (const float*)d_in[7];
    float* out = (float*)d_out;

    const int N = in_sizes[0] / NODE_DIM;

    const int fused_smem = 53760;
    const int final_smem = (NODE_DIM * OUT_DIM + FIN_GRAPHS * NODE_DIM
                            + FIN_GRAPHS) * 4;
    cudaFuncSetAttribute(fused_kernel, cudaFuncAttributeMaxDynamicSharedMemorySize, fused_smem);
    cudaFuncSetAttribute(final_kernel, cudaFuncAttributeMaxDynamicSharedMemorySize, final_smem);

    prep_kernel<<<4, THREADS>>>(Wg1);
    {
        int blocks = (N + CHUNK - 1) / CHUNK;
        fused_kernel<<<blocks, THREADS, fused_smem>>>(h_nodes, batch, bg1, Wg2, bg2, N);
    }
    final_kernel<<<NUM_GRAPHS / FIN_GRAPHS, THREADS, final_smem>>>(Wp, bp, out);
}

// round 17
// speedup vs baseline: 1.1868x; 1.1868x over previous
#include <cuda_runtime.h>
#include <cuda_fp16.h>
#include <stdint.h>

#define NODE_DIM   128
#define GATE_HID   64
#define OUT_DIM    128
#define NUM_GRAPHS 16384
#define CHUNK      256
#define THREADS    256

#define B_STRIDE_H 136   // halves; warp-private h slice stride
#define A_SLICE_H  (16 * B_STRIDE_H)

// Scratch: per-graph sum of g*h [B,128] and per-graph sum of g [B].
// Invariant: zero at kernel_launch entry (loader zero-init covers call #1;
// final_kernel re-zeros its exclusive slice after consuming it).
__device__ float g_S[NUM_GRAPHS * OUT_DIM];
__device__ float g_cnt[NUM_GRAPHS];
// Fragment-ordered fp16 Wg1, paired over ks:
// g_Bf4[(nt*4 + kp)*32 + lane] = {b(2kp).x, b(2kp).y, b(2kp+1).x, b(2kp+1).y}
__device__ uint4 g_Bf4[8 * 4 * 32];

static __device__ __forceinline__ uint32_t u32_of(__half2 h) {
    union { __half2 h; uint32_t u; } c; c.h = h; return c.u;
}
static __device__ __forceinline__ __half2 h2_of(uint32_t u) {
    union { uint32_t u; __half2 h; } c; c.u = u; return c.h;
}
static __device__ __forceinline__ uint32_t cvt2(float2 v) {
    return u32_of(__floats2half2_rn(v.x, v.y));
}
static __device__ __forceinline__ uint32_t pack2(float a, float b) {
    return u32_of(__floats2half2_rn(a, b));
}

// ---------------------------------------------------------------------------
// Warp-level fp16 MMA with fp16 accumulate
// ---------------------------------------------------------------------------
static __device__ __forceinline__ void mma16816_f16(
    uint32_t* d, uint32_t a0, uint32_t a1, uint32_t a2, uint32_t a3,
    uint32_t b0, uint32_t b1)
{
    asm volatile(
        "mma.sync.aligned.m16n8k16.row.col.f16.f16.f16.f16 "
        "{%0,%1}, {%2,%3,%4,%5}, {%6,%7}, {%0,%1};"
        : "+r"(d[0]), "+r"(d[1])
        : "r"(a0), "r"(a1), "r"(a2), "r"(a3), "r"(b0), "r"(b1));
}

// batch may be int32 or int64 (layout-detected; see earlier rounds)
static __device__ __forceinline__ int batch_at(const void* p, int i, bool is64) {
    if (is64) return (int)(((const long long*)p)[i]);
    return ((const int*)p)[i];
}

// ---------------------------------------------------------------------------
// prep: Wg1 [128,64] -> ks-paired fragment table (1024 uint4 entries)
// ---------------------------------------------------------------------------
__global__ void prep_kernel(const float* __restrict__ Wg1) {
    int idx = blockIdx.x * blockDim.x + threadIdx.x;
    if (idx < 1024) {
        int lane = idx & 31, e = idx >> 5;   // e = nt*4 + kp
        int kp = e & 3, nt = e >> 2;
        int gq = lane >> 2, tq = lane & 3;
        int n  = nt * 8 + gq;
        int ka = (2 * kp) * 16 + tq * 2;      // ks = 2kp
        int kb = (2 * kp + 1) * 16 + tq * 2;  // ks = 2kp+1
        uint4 v;
        v.x = pack2(Wg1[ka * GATE_HID + n],       Wg1[(ka + 1) * GATE_HID + n]);
        v.y = pack2(Wg1[(ka + 8) * GATE_HID + n], Wg1[(ka + 9) * GATE_HID + n]);
        v.z = pack2(Wg1[kb * GATE_HID + n],       Wg1[(kb + 1) * GATE_HID + n]);
        v.w = pack2(Wg1[(kb + 8) * GATE_HID + n], Wg1[(kb + 9) * GATE_HID + n]);
        g_Bf4[idx] = v;
    }
}

// ---------------------------------------------------------------------------
// Fused pass per 256-node chunk; warp owns 32 rows as 2 sub-tiles of 16.
// R15 structure (pipelined loads, carried accumulators) + uint4 B table
// (one LDS.128 feeds two HMMAs) + float2 (b1,w2) epilogue.
// ---------------------------------------------------------------------------
__global__ __launch_bounds__(THREADS, 3)
void fused_kernel(const float* __restrict__ h_nodes,
                  const void*  __restrict__ batch,
                  const float* __restrict__ bg1,
                  const float* __restrict__ Wg2,
                  const float* __restrict__ bg2,
                  int N)
{
    extern __shared__ char sm[];
    uint4*  smT4 = (uint4*)sm;                             // 16384 B
    __half* smHA = (__half*)(sm + 16384);                  // 34816 B
    int*    sh_b = (int*)(sm + 51200);                     // 1024 B
    float2* sh_bw = (float2*)(sm + 52224);                 // 512 B (b1,w2)
                                                           // total 52736

    const int tid  = threadIdx.x;
    const int wid  = tid >> 5;
    const int lane = tid & 31;
    const int gq   = lane >> 2;
    const int tq   = lane & 3;
    const int base = blockIdx.x * CHUNK;
    const int nn   = min(CHUNK, N - base);

    const bool is64 = (((const int*)batch)[N - 1] == 0);

    #pragma unroll 4
    for (int i = tid; i < 1024; i += THREADS)
        smT4[i] = g_Bf4[i];
    if (tid < GATE_HID) sh_bw[tid] = make_float2(bg1[tid], Wg2[tid]);
    if (tid < CHUNK) sh_b[tid] = (tid < nn) ? batch_at(batch, base + tid, is64) : 0;
    __syncthreads();

    __half* ws = smHA + wid * A_SLICE_H;
    const float b2 = bg2[0];
    const float2 z2 = make_float2(0.f, 0.f);

    float2 f0[4], f1[4], f2[4], f3[4];

#define LOADG(grp, hp0, hp1, vv0, vv1)                                   \
    do {                                                                 \
        _Pragma("unroll")                                                \
        for (int kk = 0; kk < 4; ++kk) {                                 \
            const int kb = ((grp) * 4 + kk) * 16 + tq * 2;               \
            f0[kk] = (vv0) ? *(const float2*)((hp0) + kb)     : z2;      \
            f2[kk] = (vv0) ? *(const float2*)((hp0) + kb + 8) : z2;      \
            f1[kk] = (vv1) ? *(const float2*)((hp1) + kb)     : z2;      \
            f3[kk] = (vv1) ? *(const float2*)((hp1) + kb + 8) : z2;      \
        }                                                                \
    } while (0)

#define CVT_STS(grp, A0v, A1v, A2v, A3v)                                 \
    do {                                                                 \
        _Pragma("unroll")                                                \
        for (int kk = 0; kk < 4; ++kk) {                                 \
            A0v[kk] = cvt2(f0[kk]); A1v[kk] = cvt2(f1[kk]);              \
            A2v[kk] = cvt2(f2[kk]); A3v[kk] = cvt2(f3[kk]);              \
            const int kb = ((grp) * 4 + kk) * 16 + tq * 2;               \
            *(uint32_t*)(ws + gq * B_STRIDE_H + kb)           = A0v[kk]; \
            *(uint32_t*)(ws + gq * B_STRIDE_H + kb + 8)       = A2v[kk]; \
            *(uint32_t*)(ws + (gq + 8) * B_STRIDE_H + kb)     = A1v[kk]; \
            *(uint32_t*)(ws + (gq + 8) * B_STRIDE_H + kb + 8) = A3v[kk]; \
        }                                                                \
    } while (0)

// B via LDS.128: one uint4 = fragments for ks=2kp and 2kp+1 of column tile nt
#define MMA_GRP(grp, A0v, A1v, A2v, A3v)                                 \
    do {                                                                 \
        _Pragma("unroll")                                                \
        for (int kpl = 0; kpl < 2; ++kpl) {                              \
            const int kp = (grp) * 2 + kpl;                              \
            _Pragma("unroll")                                            \
            for (int nt = 0; nt < 8; ++nt) {                             \
                uint4 b = smT4[(nt * 4 + kp) * 32 + lane];               \
                mma16816_f16(d[nt], A0v[2*kpl],   A1v[2*kpl],            \
                             A2v[2*kpl],   A3v[2*kpl],   b.x, b.y);      \
                mma16816_f16(d[nt], A0v[2*kpl+1], A1v[2*kpl+1],          \
                             A2v[2*kpl+1], A3v[2*kpl+1], b.z, b.w);      \
            }                                                            \
        }                                                                \
    } while (0)

    const int wbeg = wid * 32;
    const float* hr0 = h_nodes + (size_t)(base + wbeg + gq) * NODE_DIM;
    const float* hr1 = hr0 + 8 * NODE_DIM;
    bool v0 = (base + wbeg + gq) < N;
    bool v1 = (base + wbeg + gq + 8) < N;

    // cross-sub scatter state (spanning graphs flush once)
    const bool any = wbeg < nn;
    int   cur  = any ? sh_b[wbeg] : 0;
    float a0 = 0.f, a1 = 0.f, a2 = 0.f, a3 = 0.f, accG = 0.f;

    // prologue: grp0 of sub 0 in flight
    LOADG(0, hr0, hr1, v0, v1);

    #pragma unroll
    for (int sub = 0; sub < 2; ++sub) {
        const int rbeg = wbeg + sub * 16;
        uint32_t d[8][2];
        #pragma unroll
        for (int nt = 0; nt < 8; ++nt) { d[nt][0] = 0u; d[nt][1] = 0u; }

        uint32_t A0[4], A1[4], A2[4], A3[4];
        CVT_STS(0, A0, A1, A2, A3);
        LOADG(1, hr0, hr1, v0, v1);      // grp1 latency covered by grp0 MMAs
        MMA_GRP(0, A0, A1, A2, A3);
        CVT_STS(1, A0, A1, A2, A3);
        MMA_GRP(1, A0, A1, A2, A3);

        // --- gate epilogue: relu(+b1) . w2, quad butterfly
        float s0 = 0.0f, s1 = 0.0f;
        #pragma unroll
        for (int nt = 0; nt < 8; ++nt) {
            int c0 = nt * 8 + tq * 2;
            float2 bwa = sh_bw[c0];
            float2 bwb = sh_bw[c0 + 1];
            float2 lo = __half22float2(h2_of(d[nt][0]));   // row gq
            float2 hi = __half22float2(h2_of(d[nt][1]));   // row gq+8
            s0 = fmaf(fmaxf(lo.x + bwa.x, 0.0f), bwa.y, s0);
            s0 = fmaf(fmaxf(lo.y + bwb.x, 0.0f), bwb.y, s0);
            s1 = fmaf(fmaxf(hi.x + bwa.x, 0.0f), bwa.y, s1);
            s1 = fmaf(fmaxf(hi.y + bwb.x, 0.0f), bwb.y, s1);
        }
        s0 += __shfl_xor_sync(0xffffffffu, s0, 1);
        s0 += __shfl_xor_sync(0xffffffffu, s0, 2);
        s1 += __shfl_xor_sync(0xffffffffu, s1, 1);
        s1 += __shfl_xor_sync(0xffffffffu, s1, 2);
        s0 = 1.0f / (1.0f + __expf(-(s0 + b2)));
        s1 = 1.0f / (1.0f + __expf(-(s1 + b2)));

        // prefetch next sub's grp0 under the scatter
        if (sub == 0) {
            hr0 += 16 * NODE_DIM;
            hr1 += 16 * NODE_DIM;
            v0 = (base + wbeg + 16 + gq) < N;
            v1 = (base + wbeg + 16 + gq + 8) < N;
            LOADG(0, hr0, hr1, v0, v1);
        }

        // --- scatter these 16 nodes; accumulators persist across subs
        const int nend = min(rbeg + 16, nn);
        #pragma unroll
        for (int lr = 0; lr < 16; ++lr) {
            int n = rbeg + lr;
            if (n >= nend) break;
            int b = sh_b[n];
            if (b != cur) {
                float* dst = g_S + (size_t)cur * OUT_DIM + lane * 4;
                atomicAdd(dst + 0, a0); atomicAdd(dst + 1, a1);
                atomicAdd(dst + 2, a2); atomicAdd(dst + 3, a3);
                if (lane == 0) atomicAdd(&g_cnt[cur], accG);
                a0 = a1 = a2 = a3 = 0.f; accG = 0.f; cur = b;
            }
            float g = __shfl_sync(0xffffffffu, (lr < 8) ? s0 : s1, (lr & 7) * 4);
            const __half2* hp = (const __half2*)(ws + lr * B_STRIDE_H + lane * 4);
            float2 h01 = __half22float2(hp[0]);
            float2 h23 = __half22float2(hp[1]);
            a0 = fmaf(g, h01.x, a0); a1 = fmaf(g, h01.y, a1);
            a2 = fmaf(g, h23.x, a2); a3 = fmaf(g, h23.y, a3);
            accG += g;
        }
    }

    // final flush (once per warp)
    if (any) {
        float* dst = g_S + (size_t)cur * OUT_DIM + lane * 4;
        atomicAdd(dst + 0, a0); atomicAdd(dst + 1, a1);
        atomicAdd(dst + 2, a2); atomicAdd(dst + 3, a3);
        if (lane == 0) atomicAdd(&g_cnt[cur], accG);
    }
#undef LOADG
#undef CVT_STS
#undef MMA_GRP
}

// ---------------------------------------------------------------------------
// Final: out = S @ Wp + cnt (x) bp.  32 graphs/block, thread = 4 graphs x 4
// outputs. Then re-zero this block's scratch slice.
// ---------------------------------------------------------------------------
#define FIN_GRAPHS 32

__global__ __launch_bounds__(THREADS, 2)
void final_kernel(const float* __restrict__ Wp,
                  const float* __restrict__ bp,
                  float* __restrict__ out)
{
    extern __shared__ float smf[];
    float* sWp  = smf;                        // [128][128] d-major
    float* sS   = smf + NODE_DIM * OUT_DIM;   // [32][128]
    float* scnt = sS + FIN_GRAPHS * NODE_DIM; // 32 floats

    const int tid = threadIdx.x;
    const int gr  = tid >> 5;
    const int oc  = tid & 31;
    const int gblk = blockIdx.x * FIN_GRAPHS;

    #pragma unroll 16
    for (int i = tid; i < NODE_DIM * OUT_DIM / 4; i += THREADS)
        ((float4*)sWp)[i] = ((const float4*)Wp)[i];
    #pragma unroll 4
    for (int i = tid; i < FIN_GRAPHS * NODE_DIM / 4; i += THREADS) {
        int g = i >> 5, q = i & 31;
        ((float4*)(sS + g * NODE_DIM))[q] =
            ((const float4*)(g_S + (size_t)(gblk + g) * NODE_DIM))[q];
    }
    if (tid < FIN_GRAPHS) scnt[tid] = g_cnt[gblk + tid];
    __syncthreads();

    const float4 bpv = ((const float4*)bp)[oc];
    float acc[4][4];
    #pragma unroll
    for (int i = 0; i < 4; ++i) {
        float c = scnt[gr * 4 + i];
        acc[i][0] = c * bpv.x; acc[i][1] = c * bpv.y;
        acc[i][2] = c * bpv.z; acc[i][3] = c * bpv.w;
    }

    #pragma unroll 4
    for (int dq = 0; dq < NODE_DIM / 4; ++dq) {
        float4 w0 = ((const float4*)(sWp + (dq * 4 + 0) * OUT_DIM))[oc];
        float4 w1 = ((const float4*)(sWp + (dq * 4 + 1) * OUT_DIM))[oc];
        float4 w2 = ((const float4*)(sWp + (dq * 4 + 2) * OUT_DIM))[oc];
        float4 w3 = ((const float4*)(sWp + (dq * 4 + 3) * OUT_DIM))[oc];
        #pragma unroll
        for (int i = 0; i < 4; ++i) {
            float4 sv = ((const float4*)(sS + (gr * 4 + i) * NODE_DIM))[dq];
            acc[i][0] = fmaf(sv.x, w0.x, acc[i][0]);
            acc[i][1] = fmaf(sv.x, w0.y, acc[i][1]);
            acc[i][2] = fmaf(sv.x, w0.z, acc[i][2]);
            acc[i][3] = fmaf(sv.x, w0.w, acc[i][3]);
            acc[i][0] = fmaf(sv.y, w1.x, acc[i][0]);
            acc[i][1] = fmaf(sv.y, w1.y, acc[i][1]);
            acc[i][2] = fmaf(sv.y, w1.z, acc[i][2]);
            acc[i][3] = fmaf(sv.y, w1.w, acc[i][3]);
            acc[i][0] = fmaf(sv.z, w2.x, acc[i][0]);
            acc[i][1] = fmaf(sv.z, w2.y, acc[i][1]);
            acc[i][2] = fmaf(sv.z, w2.z, acc[i][2]);
            acc[i][3] = fmaf(sv.z, w2.w, acc[i][3]);
            acc[i][0] = fmaf(sv.w, w3.x, acc[i][0]);
            acc[i][1] = fmaf(sv.w, w3.y, acc[i][1]);
            acc[i][2] = fmaf(sv.w, w3.z, acc[i][2]);
            acc[i][3] = fmaf(sv.w, w3.w, acc[i][3]);
        }
    }

    #pragma unroll
    for (int i = 0; i < 4; ++i) {
        float4 v = make_float4(acc[i][0], acc[i][1], acc[i][2], acc[i][3]);
        ((float4*)(out + (size_t)(gblk + gr * 4 + i) * OUT_DIM))[oc] = v;
    }

    __syncthreads();
    float4 z = make_float4(0.f, 0.f, 0.f, 0.f);
    float4* srow4 = (float4*)(g_S + (size_t)gblk * NODE_DIM);
    #pragma unroll 4
    for (int i = tid; i < FIN_GRAPHS * NODE_DIM / 4; i += THREADS) srow4[i] = z;
    if (tid < FIN_GRAPHS) g_cnt[gblk + tid] = 0.0f;
}

// ---------------------------------------------------------------------------
extern "C" void kernel_launch(void* const* d_in, const int* in_sizes, int n_in,
                              void* d_out, int out_size)
{
    const float* h_nodes = (const float*)d_in[0];
    const void*  batch   = d_in[1];
    const float* Wg1     = (const float*)d_in[2];
    const float* bg1     = (const float*)d_in[3];
    const float* Wg2     = (const float*)d_in[4];
    const float* bg2     = (const float*)d_in[5];
    const float* Wp      = (const float*)d_in[6];
    const float* bp      = (const float*)d_in[7];
    float* out = (float*)d_out;

    const int N = in_sizes[0] / NODE_DIM;

    const int fused_smem = 52736;
    const int final_smem = (NODE_DIM * OUT_DIM + FIN_GRAPHS * NODE_DIM
                            + FIN_GRAPHS) * 4;
    cudaFuncSetAttribute(fused_kernel, cudaFuncAttributeMaxDynamicSharedMemorySize, fused_smem);
    cudaFuncSetAttribute(final_kernel, cudaFuncAttributeMaxDynamicSharedMemorySize, final_smem);

    prep_kernel<<<4, THREADS>>>(Wg1);
    {
        int blocks = (N + CHUNK - 1) / CHUNK;
        fused_kernel<<<blocks, THREADS, fused_smem>>>(h_nodes, batch, bg1, Wg2, bg2, N);
    }
    final_kernel<<<NUM_GRAPHS / FIN_GRAPHS, THREADS, final_smem>>>(Wp, bp, out);
}